// round 17
// baseline (speedup 1.0000x reference)
#include <cuda_runtime.h>
#include <cuda_bf16.h>
#include <cstdint>
#include <math.h>

#define VOCAB   50257
#define DIM     768
#define RANK    16
#define SCALING 2.0f
#define NTOK    16384

#define NB1     148         // k1 blocks (1 per SM)
#define ROWS1   340         // rows per k1 block (148*340 >= 50257)
#define NBP     148         // partial sets

#define NCHUNK  8           // k2 stage-A p-chunks
#define PCHUNK  19          // sets per chunk (19*8=152 >= 148)
#define JTOT    (DIM * RANK + DIM + 256)   // 13312 flat reduction space

#define K3B     148
#define K3T     111
#define PF1     8
#define PF3     4

typedef unsigned long long u64;
typedef unsigned int       u32;

// ---------------- scratch (no allocations allowed) ----------------
__device__ __align__(16) float g_partM[NBP * DIM * RANK];   // [p][d*16+r]
__device__ __align__(16) float g_partE2[NBP * DIM];
__device__ __align__(16) float g_partG[NBP * 256];
__device__ __align__(16) float g_stage[NCHUNK * JTOT];      // stage-A output
__device__ __align__(16) float g_M[DIM * RANK];
__device__ __align__(16) float g_E2[DIM];
__device__ __align__(16) float g_G[256];
__device__ __align__(16) float g_sc[DIM];
__device__ __align__(16) float g_Bs[RANK * DIM];

// ---------------- f32x2 helpers ----------------
__device__ __forceinline__ u64 pack2(float lo, float hi) {
    u64 r;
    asm("mov.b64 %0, {%1, %2};" : "=l"(r) : "f"(lo), "f"(hi));
    return r;
}
__device__ __forceinline__ void unpack2(u64 v, float& lo, float& hi) {
    asm("mov.b64 {%0, %1}, %2;" : "=f"(lo), "=f"(hi) : "l"(v));
}
__device__ __forceinline__ u64 fma2(u64 a, u64 b, u64 c) {
    u64 d;
    asm("fma.rn.f32x2 %0, %1, %2, %3;" : "=l"(d) : "l"(a), "l"(b), "l"(c));
    return d;
}
__device__ __forceinline__ float4 ldg_v4(const float4* p) {
    float4 v;
    asm volatile("ld.global.nc.v4.f32 {%0,%1,%2,%3}, [%4];"
                 : "=f"(v.x), "=f"(v.y), "=f"(v.z), "=f"(v.w) : "l"(p));
    return v;
}

// =================================================================
// Kernel 1 (R6 variant — best measured). 768 threads = 768 columns.
// f32x2 lanes = RANK-pairs; A row-major in shared (4 LDS.128/row,
// broadcast); E scalar LDG.32 coalesced; 8-row batched prefetch.
// =================================================================
__global__ __launch_bounds__(768, 1)
void k1_stats(const float* __restrict__ E, const float* __restrict__ A) {
    __shared__ __align__(16) float shA[ROWS1 * RANK];   // 21.25KB
    const int b    = blockIdx.x;
    const int tid  = threadIdx.x;
    const int v0   = b * ROWS1;
    const int rows = min(ROWS1, VOCAB - v0);   // >= 277

    for (int idx = tid; idx < rows * RANK; idx += 768)
        shA[idx] = A[(size_t)v0 * RANK + idx];
    __syncthreads();

    const float* cp = E + (size_t)v0 * DIM + tid;

    u64 accM[8];
#pragma unroll
    for (int q = 0; q < 8; q++) accM[q] = 0ull;
    float accE = 0.f;

    const int fullc = rows - rows % PF1;

    float cur[PF1];
#pragma unroll
    for (int k = 0; k < PF1; k++) cur[k] = cp[(size_t)min(k, rows - 1) * DIM];

    for (int base = 0; base < fullc; base += PF1) {
        float nxt[PF1];
#pragma unroll
        for (int k = 0; k < PF1; k++) {
            int idx = min(base + PF1 + k, rows - 1);
            nxt[k] = cp[(size_t)idx * DIM];
        }
#pragma unroll
        for (int q = 0; q < PF1; q++) {
            const int i = base + q;
            const float e = cur[q];
            const u64 ed = pack2(e, e);
            const ulonglong2* ap = reinterpret_cast<const ulonglong2*>(shA + i * RANK);
#pragma unroll
            for (int q2 = 0; q2 < 4; q2++) {
                ulonglong2 av = ap[q2];                 // LDS.128 (broadcast)
                accM[2 * q2]     = fma2(av.x, ed, accM[2 * q2]);
                accM[2 * q2 + 1] = fma2(av.y, ed, accM[2 * q2 + 1]);
            }
            accE = fmaf(e, e, accE);
        }
#pragma unroll
        for (int k = 0; k < PF1; k++) cur[k] = nxt[k];
    }
    for (int i = fullc; i < rows; i++) {
        const float e = cur[i - fullc];
        const u64 ed = pack2(e, e);
        const ulonglong2* ap = reinterpret_cast<const ulonglong2*>(shA + i * RANK);
#pragma unroll
        for (int q2 = 0; q2 < 4; q2++) {
            ulonglong2 av = ap[q2];
            accM[2 * q2]     = fma2(av.x, ed, accM[2 * q2]);
            accM[2 * q2 + 1] = fma2(av.y, ed, accM[2 * q2 + 1]);
        }
        accE = fmaf(e, e, accE);
    }

    {
        float4* dstM = reinterpret_cast<float4*>(g_partM + (size_t)b * (DIM * RANK) + tid * RANK);
#pragma unroll
        for (int q2 = 0; q2 < 4; q2++) {
            float l0, h0, l1, h1;
            unpack2(accM[2 * q2], l0, h0);
            unpack2(accM[2 * q2 + 1], l1, h1);
            dstM[q2] = make_float4(l0, h0, l1, h1);
        }
    }
    g_partE2[b * DIM + tid] = accE;

    if (tid < 256) {
        int r = tid >> 4, r2 = tid & 15;
        float g = 0.f;
        for (int i = 0; i < rows; i++)
            g += shA[i * RANK + r] * shA[i * RANK + r2];
        g_partG[b * 256 + tid] = g;
    }
}

// =================================================================
// Kernel 2a: stage-A reduction. grid (52, 8) x 256 threads.
// Chunk c sums partial sets [c*19, min(148, c*19+19)) for its j.
// 8x parallelism, 37x shorter dependent chains vs old k2.
// =================================================================
__global__ void k2a_reduce() {
    const int j = blockIdx.x * 256 + threadIdx.x;
    const int c = blockIdx.y;
    const int p0 = c * PCHUNK;
    const int p1 = min(NBP, p0 + PCHUNK);
    float s = 0.f;
    if (j < DIM * RANK) {
#pragma unroll 4
        for (int p = p0; p < p1; p++) s += g_partM[(size_t)p * (DIM * RANK) + j];
    } else if (j < DIM * RANK + DIM) {
        const int d = j - DIM * RANK;
#pragma unroll 4
        for (int p = p0; p < p1; p++) s += g_partE2[p * DIM + d];
    } else {
        const int t = j - (DIM * RANK + DIM);
#pragma unroll 4
        for (int p = p0; p < p1; p++) s += g_partG[p * 256 + t];
    }
    g_stage[(size_t)c * JTOT + j] = s;
}

// =================================================================
// Kernel 2b: stage-B fold of the 8 chunks. grid 52 x 256.
// =================================================================
__global__ void k2b_fold() {
    const int j = blockIdx.x * 256 + threadIdx.x;
    float s = 0.f;
#pragma unroll
    for (int c = 0; c < NCHUNK; c++) s += g_stage[(size_t)c * JTOT + j];
    if (j < DIM * RANK)                 g_M[j] = s;
    else if (j < DIM * RANK + DIM)      g_E2[j - DIM * RANK] = s;
    else                                g_G[j - (DIM * RANK + DIM)] = s;
}

// =================================================================
// Kernel 2c: sc[d] = mag[d]/norm[d];  Bs[r,d] = s*B[r,d]*sc[d]
// =================================================================
__global__ void k2c_norms(const float* __restrict__ B, const float* __restrict__ mag) {
    int d = blockIdx.x * 256 + threadIdx.x;
    float bb[RANK];
#pragma unroll
    for (int r = 0; r < RANK; r++) bb[r] = B[r * DIM + d];
    float cross = 0.f, quad = 0.f;
#pragma unroll
    for (int r = 0; r < RANK; r++) {
        float t = 0.f;
#pragma unroll
        for (int r2 = 0; r2 < RANK; r2++) t += g_G[r * RANK + r2] * bb[r2];
        quad  += bb[r] * t;
        cross += g_M[d * RANK + r] * bb[r];
    }
    float n2 = g_E2[d] + 2.f * SCALING * cross + SCALING * SCALING * quad;
    float n  = fmaxf(sqrtf(n2), 1e-8f);
    float sc = mag[d] / n;
    g_sc[d] = sc;
#pragma unroll
    for (int r = 0; r < RANK; r++) g_Bs[r * DIM + d] = SCALING * bb[r] * sc;
}

// =================================================================
// Kernel 3: gather (R16 variant — best measured).
// 384 threads = 192 d-groups (4 cols) x 2 token substreams.
// =================================================================
__global__ __launch_bounds__(384, 1)
void k3_gather(const int* __restrict__ ids, const float* __restrict__ E,
               const float* __restrict__ A, float* __restrict__ out) {
    __shared__ int shT[K3T];
    __shared__ __align__(16) float shA[K3T * RANK];
    const int b    = blockIdx.x;
    const int tid  = threadIdx.x;
    const int t0   = b * K3T;
    const int ntok = min(K3T, NTOK - t0);

    const int sub  = tid >= 192;
    const int dg   = sub ? tid - 192 : tid;
    const int col  = 4 * dg;

    u64 rb[4][8];
#pragma unroll
    for (int c = 0; c < 4; c++)
#pragma unroll
        for (int q = 0; q < 8; q++)
            rb[c][q] = pack2(g_Bs[(2 * q) * DIM + col + c], g_Bs[(2 * q + 1) * DIM + col + c]);
    float scv[4];
#pragma unroll
    for (int c = 0; c < 4; c++) scv[c] = g_sc[col + c];

    if (tid < ntok) shT[tid] = ids[t0 + tid];
    __syncthreads();
    for (int idx = tid; idx < ntok * RANK; idx += 384)
        shA[idx] = A[(size_t)shT[idx >> 4] * RANK + (idx & 15)];
    __syncthreads();

    const int n0  = (ntok + 1) >> 1;
    const int i0  = sub ? n0 : 0;
    const int cnt = (sub ? ntok : n0) - i0;

    const float4* Ep = reinterpret_cast<const float4*>(E) + dg;

    float4 cur[PF3];
#pragma unroll
    for (int k = 0; k < PF3; k++)
        cur[k] = ldg_v4(Ep + (size_t)shT[i0 + min(k, cnt - 1)] * (DIM / 4));

    int base = 0;
    for (; base + PF3 <= cnt; base += PF3) {
#pragma unroll
        for (int q = 0; q < PF3; q++) {
            const int j = base + q;
            const int i = i0 + j;
            const float4 e = cur[q];
            cur[q] = ldg_v4(Ep + (size_t)shT[i0 + min(j + PF3, cnt - 1)] * (DIM / 4));

            const ulonglong2* ap = reinterpret_cast<const ulonglong2*>(shA + i * RANK);
            const ulonglong2 av0 = ap[0], av1 = ap[1], av2 = ap[2], av3 = ap[3];
            const float ec[4] = {e.x, e.y, e.z, e.w};
            float res[4];
#pragma unroll
            for (int c = 0; c < 4; c++) {
                u64 acc = 0ull;
                acc = fma2(av0.x, rb[c][0], acc);
                acc = fma2(av0.y, rb[c][1], acc);
                acc = fma2(av1.x, rb[c][2], acc);
                acc = fma2(av1.y, rb[c][3], acc);
                acc = fma2(av2.x, rb[c][4], acc);
                acc = fma2(av2.y, rb[c][5], acc);
                acc = fma2(av3.x, rb[c][6], acc);
                acc = fma2(av3.y, rb[c][7], acc);
                float lo, hi;
                unpack2(acc, lo, hi);
                res[c] = fmaf(ec[c], scv[c], lo + hi);
            }
            *reinterpret_cast<float4*>(out + (size_t)(t0 + i) * DIM + col) =
                make_float4(res[0], res[1], res[2], res[3]);
        }
    }
    for (int j = base; j < cnt; j++) {
        const int i = i0 + j;
        const float4 e = cur[j - base];
        const ulonglong2* ap = reinterpret_cast<const ulonglong2*>(shA + i * RANK);
        const ulonglong2 av0 = ap[0], av1 = ap[1], av2 = ap[2], av3 = ap[3];
        const float ec[4] = {e.x, e.y, e.z, e.w};
        float res[4];
#pragma unroll
        for (int c = 0; c < 4; c++) {
            u64 acc = 0ull;
            acc = fma2(av0.x, rb[c][0], acc);
            acc = fma2(av0.y, rb[c][1], acc);
            acc = fma2(av1.x, rb[c][2], acc);
            acc = fma2(av1.y, rb[c][3], acc);
            acc = fma2(av2.x, rb[c][4], acc);
            acc = fma2(av2.y, rb[c][5], acc);
            acc = fma2(av3.x, rb[c][6], acc);
            acc = fma2(av3.y, rb[c][7], acc);
            float lo, hi;
            unpack2(acc, lo, hi);
            res[c] = fmaf(ec[c], scv[c], lo + hi);
        }
        *reinterpret_cast<float4*>(out + (size_t)(t0 + i) * DIM + col) =
            make_float4(res[0], res[1], res[2], res[3]);
    }
}

// =================================================================
extern "C" void kernel_launch(void* const* d_in, const int* in_sizes, int n_in,
                              void* d_out, int out_size) {
    const int*   ids = (const int*)d_in[0];    // [8,2048] int32
    const float* E   = (const float*)d_in[1];  // [50257,768]
    const float* A   = (const float*)d_in[2];  // [50257,16]
    const float* B   = (const float*)d_in[3];  // [16,768]
    const float* mag = (const float*)d_in[4];  // [768]
    float* out = (float*)d_out;                // [8,2048,768] fp32

    k1_stats <<<NB1, 768>>>(E, A);
    k2a_reduce<<<dim3(52, NCHUNK), 256>>>();
    k2b_fold <<<52, 256>>>();
    k2c_norms<<<3, 256>>>(B, mag);
    k3_gather<<<K3B, 384>>>(ids, E, A, out);
}